// round 6
// baseline (speedup 1.0000x reference)
#include <cuda_runtime.h>
#include <math.h>

// ---------------------------------------------------------------------------
// HybridModel: conv1(3->16)+relu -> conv2(16->8)+relu -> fc(8192->4)
//              -> 4-qubit quantum sim -> fc2(4->8192)
//              -> dconv1(8->16)+relu -> dconv2(16->3)+sigmoid
// B = 2048, images 32x32, all convs 3x3 SAME.
// One block per image; activations staged in shared memory; only (B,4)
// vectors cross kernel boundaries. Conv register tiles capped at 8 output
// channels (acc[8][4]) -> no spill at __launch_bounds__(256,2), 2 CTAs/SM.
// Plane zero-fill is halo-only (interiors are always fully overwritten).
// ---------------------------------------------------------------------------

#define PW 34
#define PP 1156   // 34*34 padded plane
#define HALO 132  // 2*34 + 2*32 border elements per plane

__device__ float g_ang[4096 * 4];
__device__ float g_q[4096 * 4];

// Zero only the 1-element border of NP consecutive padded planes.
__device__ __forceinline__ void zero_halo(float* base, int nplanes, int tid)
{
    for (int i = tid; i < nplanes * HALO; i += 256) {
        int pl = i / HALO, h = i - pl * HALO;
        int pos;
        if (h < 34)       pos = h;                       // top row
        else if (h < 68)  pos = 33 * PW + (h - 34);      // bottom row
        else if (h < 100) pos = (h - 68 + 1) * PW;       // left col rows 1..32
        else              pos = (h - 100 + 1) * PW + 33; // right col rows 1..32
        base[pl * PP + pos] = 0.f;
    }
}

// 3x3 conv over padded smem planes, COUT<=8 register tile. Each thread
// computes a 4-pixel row strip (y, xg..xg+3) for COUT output channels.
// Weights/bias from smem (WSM=true) or gmem via __ldg broadcast (false).
template<int CIN, int COUT, bool WSM>
__device__ __forceinline__ void conv3x3_c8(
    const float* __restrict__ in,    // CIN * PP floats (zero-padded halo)
    const float* __restrict__ w,     // COUT*CIN*9  (co*CIN+ci)*9 + ky*3 + kx
    const float* __restrict__ bias,  // COUT
    float acc[COUT][4], int y, int xg)
{
    #pragma unroll
    for (int co = 0; co < COUT; co++) {
        float bb = WSM ? bias[co] : __ldg(&bias[co]);
        #pragma unroll
        for (int px = 0; px < 4; px++) acc[co][px] = bb;
    }
    #pragma unroll
    for (int ci = 0; ci < CIN; ci++) {
        #pragma unroll
        for (int ky = 0; ky < 3; ky++) {
            const float* row = &in[ci * PP + (y + ky) * PW + xg];
            float v0 = row[0], v1 = row[1], v2 = row[2];
            float v3 = row[3], v4 = row[4], v5 = row[5];
            #pragma unroll
            for (int co = 0; co < COUT; co++) {
                const float* wp = &w[(co * CIN + ci) * 9 + ky * 3];
                float w0 = WSM ? wp[0] : __ldg(&wp[0]);
                float w1 = WSM ? wp[1] : __ldg(&wp[1]);
                float w2 = WSM ? wp[2] : __ldg(&wp[2]);
                acc[co][0] += v0 * w0 + v1 * w1 + v2 * w2;
                acc[co][1] += v1 * w0 + v2 * w1 + v3 * w2;
                acc[co][2] += v2 * w0 + v3 * w1 + v4 * w2;
                acc[co][3] += v3 * w0 + v4 * w1 + v5 * w2;
            }
        }
    }
}

// ---------------------------------------------------------------------------
// K1: conv1 + relu + conv2 + relu + fc  ->  g_ang[b][0..3]
// smem: xin 3*PP | h1 16*PP | w1 432 | b1 16 | w2 1152 | b2 8 | red 32
// ---------------------------------------------------------------------------
__global__ __launch_bounds__(256, 2)
void k1_encoder(const float* __restrict__ x,
                const float* __restrict__ w1, const float* __restrict__ b1,
                const float* __restrict__ w2, const float* __restrict__ b2,
                const float* __restrict__ fcw, const float* __restrict__ fcb)
{
    extern __shared__ float sm[];
    float* xin = sm;                 // 3468
    float* h1  = sm + 3468;          // 18496
    float* sw1 = sm + 21964;         // 432
    float* sb1 = sm + 22396;         // 16
    float* sw2 = sm + 22412;         // 1152
    float* sb2 = sm + 23564;         // 8
    float* red = sm + 23572;         // 32

    const int b = blockIdx.x;
    const int tid = threadIdx.x;

    zero_halo(xin, 3, tid);
    zero_halo(h1, 16, tid);

    const float* xb = x + (size_t)b * 3072;
    for (int i = tid; i < 3072; i += 256) {
        int c = i >> 10, p = i & 1023;
        xin[c * PP + ((p >> 5) + 1) * PW + (p & 31) + 1] = xb[i];
    }
    for (int i = tid; i < 432; i += 256) sw1[i] = w1[i];
    if (tid < 16) sb1[tid] = b1[tid];
    for (int i = tid; i < 1152; i += 256) sw2[i] = w2[i];
    if (tid < 8) sb2[tid] = b2[tid];
    __syncthreads();

    const int y  = tid >> 3;
    const int xg = (tid & 7) << 2;

    // conv1: 3 -> 16 in two 8-channel halves, relu, write into padded h1
    #pragma unroll
    for (int half = 0; half < 2; half++) {
        float acc[8][4];
        conv3x3_c8<3, 8, true>(xin, sw1 + half * 8 * 3 * 9, sb1 + half * 8,
                               acc, y, xg);
        #pragma unroll
        for (int co = 0; co < 8; co++) {
            float* hp = &h1[(half * 8 + co) * PP + (y + 1) * PW + xg + 1];
            #pragma unroll
            for (int px = 0; px < 4; px++) hp[px] = fmaxf(acc[co][px], 0.f);
        }
    }
    __syncthreads();

    // conv2: 16 -> 8, relu, fused fc partials (h2 never hits gmem)
    float ap0 = 0.f, ap1 = 0.f, ap2 = 0.f, ap3 = 0.f;
    {
        float acc[8][4];
        conv3x3_c8<16, 8, true>(h1, sw2, sb2, acc, y, xg);
        #pragma unroll
        for (int co = 0; co < 8; co++) {
            #pragma unroll
            for (int px = 0; px < 4; px++) {
                float hv = fmaxf(acc[co][px], 0.f);
                int j = co * 1024 + y * 32 + xg + px;
                ap0 += hv * __ldg(&fcw[j]);
                ap1 += hv * __ldg(&fcw[8192 + j]);
                ap2 += hv * __ldg(&fcw[16384 + j]);
                ap3 += hv * __ldg(&fcw[24576 + j]);
            }
        }
    }
    // block reduce the 4 fc partials
    #pragma unroll
    for (int off = 16; off; off >>= 1) {
        ap0 += __shfl_xor_sync(0xFFFFFFFFu, ap0, off);
        ap1 += __shfl_xor_sync(0xFFFFFFFFu, ap1, off);
        ap2 += __shfl_xor_sync(0xFFFFFFFFu, ap2, off);
        ap3 += __shfl_xor_sync(0xFFFFFFFFu, ap3, off);
    }
    int warp = tid >> 5, lane = tid & 31;
    if (lane == 0) {
        red[0 * 8 + warp] = ap0;
        red[1 * 8 + warp] = ap1;
        red[2 * 8 + warp] = ap2;
        red[3 * 8 + warp] = ap3;
    }
    __syncthreads();
    if (tid < 4) {
        float s = fcb[tid];
        #pragma unroll
        for (int wv = 0; wv < 8; wv++) s += red[tid * 8 + wv];
        g_ang[b * 4 + tid] = s;
    }
}

// ---------------------------------------------------------------------------
// K2: 4-qubit statevector sim, one thread per batch element.
// ---------------------------------------------------------------------------
__device__ __forceinline__ void apply1q(float sr[16], float si[16], int m,
    float u00r, float u00i, float u01r, float u01i,
    float u10r, float u10i, float u11r, float u11i)
{
    #pragma unroll
    for (int i = 0; i < 16; i++) {
        if (i & m) continue;
        int j = i | m;
        float ar = sr[i], ai = si[i], br = sr[j], bi = si[j];
        sr[i] = u00r * ar - u00i * ai + u01r * br - u01i * bi;
        si[i] = u00r * ai + u00i * ar + u01r * bi + u01i * br;
        sr[j] = u10r * ar - u10i * ai + u11r * br - u11i * bi;
        si[j] = u10r * ai + u10i * ar + u11r * bi + u11i * br;
    }
}

__global__ void k2_quantum(const float* __restrict__ qw, int nb)
{
    int b = blockIdx.x * blockDim.x + threadIdx.x;
    if (b >= nb) return;

    float sr[16], si[16];
    #pragma unroll
    for (int i = 0; i < 16; i++) { sr[i] = 0.f; si[i] = 0.f; }
    sr[0] = 1.f;

    // AngleEmbedding: RX(ang[w]) on wire w.  U = [[c,-is],[-is,c]]
    #pragma unroll
    for (int w = 0; w < 4; w++) {
        float a = g_ang[b * 4 + w] * 0.5f;
        float c = cosf(a), s = sinf(a);
        apply1q(sr, si, 1 << (3 - w),
                c, 0.f, 0.f, -s,
                0.f, -s, c, 0.f);
    }

    // StronglyEntanglingLayers
    #pragma unroll
    for (int l = 0; l < 3; l++) {
        #pragma unroll
        for (int w = 0; w < 4; w++) {
            float phi   = qw[(l * 4 + w) * 3 + 0];
            float theta = qw[(l * 4 + w) * 3 + 1];
            float omega = qw[(l * 4 + w) * 3 + 2];
            float ct = cosf(theta * 0.5f), st = sinf(theta * 0.5f);
            float a = (phi + omega) * 0.5f, d = (phi - omega) * 0.5f;
            float ca = cosf(a), sa = sinf(a), cd = cosf(d), sd = sinf(d);
            apply1q(sr, si, 1 << (3 - w),
                    ca * ct, -sa * ct,    // e^{-ia} ct
                    -cd * st, -sd * st,   // -e^{id} st
                    cd * st, -sd * st,    // e^{-id} st
                    ca * ct,  sa * ct);   // e^{ia} ct
        }
        const int r = (l % 3) + 1;
        #pragma unroll
        for (int w = 0; w < 4; w++) {
            int cm = 1 << (3 - w);
            int tm = 1 << (3 - ((w + r) & 3));
            #pragma unroll
            for (int i = 0; i < 16; i++) {
                if ((i & cm) && !(i & tm)) {
                    int j = i | tm;
                    float tr = sr[i], ti = si[i];
                    sr[i] = sr[j]; si[i] = si[j];
                    sr[j] = tr;    si[j] = ti;
                }
            }
        }
    }

    // PauliZ expectation values
    #pragma unroll
    for (int w = 0; w < 4; w++) {
        int m = 1 << (3 - w);
        float e = 0.f;
        #pragma unroll
        for (int i = 0; i < 16; i++) {
            float p = sr[i] * sr[i] + si[i] * si[i];
            e += (i & m) ? -p : p;
        }
        g_q[b * 4 + w] = e;
    }
}

// ---------------------------------------------------------------------------
// K3: fc2 -> dconv1+relu -> dconv2+sigmoid  (one block per image)
// smem: g 8*PP | mmb 16*PP | sq 4   (weights read via __ldg -> 2 CTAs/SM)
// ---------------------------------------------------------------------------
__global__ __launch_bounds__(256, 2)
void k3_decoder(const float* __restrict__ f2w, const float* __restrict__ f2b,
                const float* __restrict__ wd1, const float* __restrict__ bd1,
                const float* __restrict__ wd2, const float* __restrict__ bd2,
                float* __restrict__ out)
{
    extern __shared__ float sm[];
    float* g   = sm;                 // 9248
    float* mmb = sm + 9248;          // 18496
    float* sq  = sm + 27744;         // 4

    const int b = blockIdx.x;
    const int tid = threadIdx.x;

    zero_halo(g, 8, tid);
    zero_halo(mmb, 16, tid);
    if (tid < 4) sq[tid] = g_q[b * 4 + tid];
    __syncthreads();

    // fc2: (4) -> (8192), into padded g
    {
        float q0 = sq[0], q1 = sq[1], q2 = sq[2], q3 = sq[3];
        const float4* fw4 = (const float4*)f2w;
        for (int i = tid; i < 8192; i += 256) {
            float4 w4 = __ldg(&fw4[i]);
            float v = q0 * w4.x + q1 * w4.y + q2 * w4.z + q3 * w4.w + __ldg(&f2b[i]);
            int c = i >> 10, p = i & 1023;
            g[c * PP + ((p >> 5) + 1) * PW + (p & 31) + 1] = v;
        }
    }
    __syncthreads();

    const int y  = tid >> 3;
    const int xg = (tid & 7) << 2;

    // dconv1: 8 -> 16 in two 8-channel halves, relu
    #pragma unroll
    for (int half = 0; half < 2; half++) {
        float acc[8][4];
        conv3x3_c8<8, 8, false>(g, wd1 + half * 8 * 8 * 9, bd1 + half * 8,
                                acc, y, xg);
        #pragma unroll
        for (int co = 0; co < 8; co++) {
            float* hp = &mmb[(half * 8 + co) * PP + (y + 1) * PW + xg + 1];
            #pragma unroll
            for (int px = 0; px < 4; px++) hp[px] = fmaxf(acc[co][px], 0.f);
        }
    }
    __syncthreads();

    // dconv2: 16 -> 3, sigmoid, write final output
    {
        float acc[3][4];
        conv3x3_c8<16, 3, false>(mmb, wd2, bd2, acc, y, xg);
        float* ob = out + (size_t)b * 3072;
        #pragma unroll
        for (int co = 0; co < 3; co++) {
            #pragma unroll
            for (int px = 0; px < 4; px++) {
                float v = acc[co][px];
                ob[co * 1024 + y * 32 + xg + px] = 1.f / (1.f + __expf(-v));
            }
        }
    }
}

// ---------------------------------------------------------------------------
extern "C" void kernel_launch(void* const* d_in, const int* in_sizes, int n_in,
                              void* d_out, int out_size)
{
    const float* x       = (const float*)d_in[0];
    const float* conv1_w = (const float*)d_in[1];
    const float* conv1_b = (const float*)d_in[2];
    const float* conv2_w = (const float*)d_in[3];
    const float* conv2_b = (const float*)d_in[4];
    const float* fc_w    = (const float*)d_in[5];
    const float* fc_b    = (const float*)d_in[6];
    const float* q_w     = (const float*)d_in[7];
    const float* fc2_w   = (const float*)d_in[8];
    const float* fc2_b   = (const float*)d_in[9];
    const float* dconv1_w = (const float*)d_in[10];
    const float* dconv1_b = (const float*)d_in[11];
    const float* dconv2_w = (const float*)d_in[12];
    const float* dconv2_b = (const float*)d_in[13];
    float* out = (float*)d_out;

    const int nb = in_sizes[0] / 3072;

    const int k1_smem = 23604 * 4;   // 94416 B  (2 CTAs/SM)
    const int k3_smem = 27748 * 4;   // 110992 B (2 CTAs/SM)
    cudaFuncSetAttribute(k1_encoder, cudaFuncAttributeMaxDynamicSharedMemorySize, k1_smem);
    cudaFuncSetAttribute(k3_decoder, cudaFuncAttributeMaxDynamicSharedMemorySize, k3_smem);

    k1_encoder<<<nb, 256, k1_smem>>>(x, conv1_w, conv1_b, conv2_w, conv2_b,
                                     fc_w, fc_b);
    k2_quantum<<<(nb + 255) / 256, 256>>>(q_w, nb);
    k3_decoder<<<nb, 256, k3_smem>>>(fc2_w, fc2_b, dconv1_w, dconv1_b,
                                     dconv2_w, dconv2_b, out);
}